// round 1
// baseline (speedup 1.0000x reference)
#include <cuda_runtime.h>
#include <cuda_bf16.h>

// Problem constants
#define BB 8        // half-batch
#define NN 1024     // sequence length
#define EE 64       // embedding channels
#define CC 512      // CH = NUM_HEADS * EMB_CH
#define DD 4096     // BB * CC
#define EPS_LN 1e-5f

// ---------------- scratch (__device__ globals: allocation-guard safe) -----
__device__ float g_qT[BB][CC][NN];        // 16 MB   qT[b][c][n] = q[b,n,c]
__device__ float g_kbank[NN][DD];         // 16 MB   k_bank[n][b*512+c]
__device__ float g_vbank[NN][DD];         // 16 MB
__device__ float g_scores[BB][CC][DD];    // 64 MB   raw scores, then exp()
__device__ float g_ctx[BB][CC][NN];       // 16 MB
__device__ float g_sum[BB];
__device__ float g_sumsq[BB];
__device__ float g_rowinv[BB][CC];        // 1/rowsum for softmax

// ---------------- init: zero the atomic stat accumulators ----------------
__global__ void k_init() {
    int t = threadIdx.x;
    if (t < BB) { g_sum[t] = 0.f; g_sumsq[t] = 0.f; }
}

// ---------------- kernel 1: q/k/v projections ----------------------------
// Block: one (b, matrix, 64n x 64c) tile. K = 64 (full).
__global__ __launch_bounds__(256) void k_proj(
    const float* __restrict__ emb, const float* __restrict__ Wq,
    const float* __restrict__ Wk,  const float* __restrict__ Wv)
{
    __shared__ float embS[64][68];
    __shared__ float WS[64][68];

    int ntile = blockIdx.x;            // 0..15
    int ctile = blockIdx.y;            // 0..7
    int bz    = blockIdx.z;            // 0..23
    int b = bz / 3, m = bz % 3;
    const float* W  = (m == 0) ? Wq : ((m == 1) ? Wk : Wv);
    const float* eb = emb + (size_t)((m == 0) ? (BB + b) : b) * NN * EE;
    int n0 = ntile * 64, c0 = ctile * 64;
    int t = threadIdx.x;

    // load 64x64 emb tile and 64x64 W tile (contiguous along E)
    #pragma unroll
    for (int r = 0; r < 4; r++) {
        int chunk = t + 256 * r;                 // 0..1023 float4 chunks
        int row = chunk >> 4;
        int col = (chunk & 15) * 4;
        *(float4*)&embS[row][col] = *(const float4*)&eb[(size_t)(n0 + row) * EE + col];
        *(float4*)&WS[row][col]   = *(const float4*)&W[(size_t)(c0 + row) * EE + col];
    }
    __syncthreads();

    int ty = t >> 4, tx = t & 15;
    float acc[4][4] = {};
    #pragma unroll 16
    for (int e = 0; e < 64; e++) {
        float a[4], bv[4];
        #pragma unroll
        for (int i = 0; i < 4; i++) a[i]  = embS[ty + 16 * i][e];
        #pragma unroll
        for (int j = 0; j < 4; j++) bv[j] = WS[tx + 16 * j][e];
        #pragma unroll
        for (int i = 0; i < 4; i++)
            #pragma unroll
            for (int j = 0; j < 4; j++) acc[i][j] += a[i] * bv[j];
    }

    if (m == 0) {
        #pragma unroll
        for (int i = 0; i < 4; i++)
            #pragma unroll
            for (int j = 0; j < 4; j++)
                g_qT[b][c0 + tx + 16 * j][n0 + ty + 16 * i] = acc[i][j];
    } else {
        float (*bank)[DD] = (m == 1) ? g_kbank : g_vbank;
        #pragma unroll
        for (int i = 0; i < 4; i++)
            #pragma unroll
            for (int j = 0; j < 4; j++)
                bank[n0 + ty + 16 * i][b * CC + c0 + tx + 16 * j] = acc[i][j];
    }
}

// ---------------- kernel 2: scores GEMM + global sum/sumsq ---------------
// Per batch: S = qT[b] (512x1024) @ k_bank (1024x4096). 128x128x16 tiles.
__global__ __launch_bounds__(256, 2) void k_scores()
{
    __shared__ float As[128][20];   // As[m][kk]  (stride 20: ty-broadcast conflict-free)
    __shared__ float Bs[16][128];   // Bs[kk][n]
    __shared__ float red[256];

    int m0 = blockIdx.x * 128;      // c
    int n0 = blockIdx.y * 128;      // d
    int b  = blockIdx.z;
    int t = threadIdx.x, ty = t >> 4, tx = t & 15;

    float acc[8][8] = {};
    for (int k0 = 0; k0 < NN; k0 += 16) {
        #pragma unroll
        for (int r = 0; r < 2; r++) {
            int chunk = t + 256 * r;                   // 512 float4 chunks each
            int arow = chunk >> 2, akc = (chunk & 3) * 4;
            *(float4*)&As[arow][akc] = *(const float4*)&g_qT[b][m0 + arow][k0 + akc];
            int brow = chunk >> 5, bcol = (chunk & 31) * 4;
            *(float4*)&Bs[brow][bcol] = *(const float4*)&g_kbank[k0 + brow][n0 + bcol];
        }
        __syncthreads();
        #pragma unroll
        for (int kk = 0; kk < 16; kk++) {
            float a[8], bv[8];
            #pragma unroll
            for (int i = 0; i < 8; i++) a[i]  = As[ty + 16 * i][kk];
            #pragma unroll
            for (int j = 0; j < 8; j++) bv[j] = Bs[kk][tx + 16 * j];
            #pragma unroll
            for (int i = 0; i < 8; i++)
                #pragma unroll
                for (int j = 0; j < 8; j++) acc[i][j] += a[i] * bv[j];
        }
        __syncthreads();
    }

    float ls = 0.f, lq = 0.f;
    #pragma unroll
    for (int i = 0; i < 8; i++)
        #pragma unroll
        for (int j = 0; j < 8; j++) {
            float v = acc[i][j];
            g_scores[b][m0 + ty + 16 * i][n0 + tx + 16 * j] = v;
            ls += v; lq += v * v;
        }

    red[t] = ls; __syncthreads();
    for (int s = 128; s > 0; s >>= 1) { if (t < s) red[t] += red[t + s]; __syncthreads(); }
    if (t == 0) atomicAdd(&g_sum[b], red[0]);
    __syncthreads();
    red[t] = lq; __syncthreads();
    for (int s = 128; s > 0; s >>= 1) { if (t < s) red[t] += red[t + s]; __syncthreads(); }
    if (t == 0) atomicAdd(&g_sumsq[b], red[0]);
}

// ---------------- kernel 3: LN + exp + row-sum (softmax denom) -----------
// One block per (b, c) row of 4096. Mean-shift is softmax-invariant; no
// max-subtraction needed (post-LN logits bounded ~6 sigma).
__global__ __launch_bounds__(256) void k_softmax()
{
    int c = blockIdx.x, b = blockIdx.y;
    int t = threadIdx.x;
    __shared__ float red[256];

    const float invCD = 1.0f / ((float)CC * (float)DD);
    float mean = g_sum[b] * invCD;
    float var  = g_sumsq[b] * invCD - mean * mean;
    float rstd = rsqrtf(var + EPS_LN);

    float* row = &g_scores[b][c][0];
    float ls = 0.f;
    #pragma unroll
    for (int r = 0; r < 4; r++) {
        int idx = (t + 256 * r) * 4;
        float4 v = *(float4*)&row[idx];
        v.x = __expf((v.x - mean) * rstd);
        v.y = __expf((v.y - mean) * rstd);
        v.z = __expf((v.z - mean) * rstd);
        v.w = __expf((v.w - mean) * rstd);
        *(float4*)&row[idx] = v;
        ls += v.x + v.y + v.z + v.w;
    }
    red[t] = ls; __syncthreads();
    for (int s = 128; s > 0; s >>= 1) { if (t < s) red[t] += red[t + s]; __syncthreads(); }
    if (t == 0) g_rowinv[b][c] = 1.0f / red[0];
}

// ---------------- kernel 4: ctx GEMM (attn @ v_bank^T) -------------------
// Per batch: ctx = expS (512x4096) @ v_bank^T (4096x1024), scaled by rowinv.
// Both operands are K-contiguous -> both tiles stored [row][kk].
__global__ __launch_bounds__(256, 2) void k_ctx()
{
    __shared__ float As[128][20];   // expS rows (c)
    __shared__ float Bs[128][17];   // v rows (n); stride 17 => tx reads conflict-free

    int m0 = blockIdx.x * 128;      // c
    int n0 = blockIdx.y * 128;      // n
    int b  = blockIdx.z;
    int t = threadIdx.x, ty = t >> 4, tx = t & 15;

    float acc[8][8] = {};
    for (int k0 = 0; k0 < DD; k0 += 16) {
        #pragma unroll
        for (int r = 0; r < 2; r++) {
            int chunk = t + 256 * r;
            int row = chunk >> 2, kc = (chunk & 3) * 4;
            *(float4*)&As[row][kc] = *(const float4*)&g_scores[b][m0 + row][k0 + kc];
            float4 v = *(const float4*)&g_vbank[n0 + row][k0 + kc];
            Bs[row][kc + 0] = v.x; Bs[row][kc + 1] = v.y;
            Bs[row][kc + 2] = v.z; Bs[row][kc + 3] = v.w;
        }
        __syncthreads();
        #pragma unroll
        for (int kk = 0; kk < 16; kk++) {
            float a[8], bv[8];
            #pragma unroll
            for (int i = 0; i < 8; i++) a[i]  = As[ty + 16 * i][kk];
            #pragma unroll
            for (int j = 0; j < 8; j++) bv[j] = Bs[tx + 16 * j][kk];
            #pragma unroll
            for (int i = 0; i < 8; i++)
                #pragma unroll
                for (int j = 0; j < 8; j++) acc[i][j] += a[i] * bv[j];
        }
        __syncthreads();
    }

    #pragma unroll
    for (int i = 0; i < 8; i++) {
        float inv = g_rowinv[b][m0 + ty + 16 * i];
        #pragma unroll
        for (int j = 0; j < 8; j++)
            g_ctx[b][m0 + ty + 16 * i][n0 + tx + 16 * j] = acc[i][j] * inv;
    }
}

// ---------------- kernel 5: output projection ----------------------------
// out[b,n,e] = sum_c ctx[b][c][n] * Wo[e][c]. Block: (b, 64-n tile), K=512.
__global__ __launch_bounds__(256) void k_out(
    const float* __restrict__ Wo, float* __restrict__ out)
{
    __shared__ float ctxS[16][68];  // [cc][n]
    __shared__ float WoS[16][68];   // [cc][e]

    int n0 = blockIdx.x * 64;
    int b  = blockIdx.y;
    int t = threadIdx.x, ty = t >> 4, tx = t & 15;

    float acc[4][4] = {};
    for (int c0 = 0; c0 < CC; c0 += 16) {
        {
            int row = t >> 4, col = (t & 15) * 4;          // ctx: 16x64 floats
            *(float4*)&ctxS[row][col] = *(const float4*)&g_ctx[b][c0 + row][n0 + col];
            int e = t >> 2, cc4 = (t & 3) * 4;             // Wo transpose-load
            float4 w = *(const float4*)&Wo[(size_t)e * CC + c0 + cc4];
            WoS[cc4 + 0][e] = w.x; WoS[cc4 + 1][e] = w.y;
            WoS[cc4 + 2][e] = w.z; WoS[cc4 + 3][e] = w.w;
        }
        __syncthreads();
        #pragma unroll
        for (int cc = 0; cc < 16; cc++) {
            float a[4], bv[4];
            #pragma unroll
            for (int i = 0; i < 4; i++) a[i]  = ctxS[cc][ty + 16 * i];
            #pragma unroll
            for (int j = 0; j < 4; j++) bv[j] = WoS[cc][tx + 16 * j];
            #pragma unroll
            for (int i = 0; i < 4; i++)
                #pragma unroll
                for (int j = 0; j < 4; j++) acc[i][j] += a[i] * bv[j];
        }
        __syncthreads();
    }
    #pragma unroll
    for (int i = 0; i < 4; i++)
        #pragma unroll
        for (int j = 0; j < 4; j++)
            out[((size_t)b * NN + n0 + ty + 16 * i) * EE + tx + 16 * j] = acc[i][j];
}

// ---------------- launch ---------------------------------------------------
extern "C" void kernel_launch(void* const* d_in, const int* in_sizes, int n_in,
                              void* d_out, int out_size)
{
    const float* emb = (const float*)d_in[0];
    const float* Wq  = (const float*)d_in[1];
    const float* Wk  = (const float*)d_in[2];
    const float* Wv  = (const float*)d_in[3];
    const float* Wo  = (const float*)d_in[4];
    float* out = (float*)d_out;

    k_init<<<1, 32>>>();

    dim3 g1(16, 8, 24);
    k_proj<<<g1, 256>>>(emb, Wq, Wk, Wv);

    dim3 g2(4, 32, 8);           // 512/128 x 4096/128 x B
    k_scores<<<g2, 256>>>();

    dim3 g3(512, 8);             // one block per (c, b) row
    k_softmax<<<g3, 256>>>();

    dim3 g4(4, 8, 8);            // 512/128 x 1024/128 x B
    k_ctx<<<g4, 256>>>();

    dim3 g5(16, 8);              // 1024/64 x B
    k_out<<<g5, 256>>>(Wo, out);
}

// round 2
// speedup vs baseline: 2.8498x; 2.8498x over previous
#include <cuda_runtime.h>
#include <cuda_bf16.h>
#include <cstdint>

// Problem constants
#define BB 8        // half-batch
#define NN 1024     // sequence length
#define EE 64       // embedding channels
#define CC 512      // CH
#define DD 4096     // BB * CC
#define EPS_LN 1e-5f

// ---------------- scratch (__device__ globals) ----------------------------
__device__ float g_qT[BB][CC][NN];        // qT[b][c][n]
__device__ float g_kbank[NN][DD];         // k_bank[n][b*512+c]
__device__ float g_vbank[NN][DD];
__device__ float g_scores[BB][CC][DD];    // raw scores, then exp()
__device__ float g_ctx[BB][CC][NN];
__device__ float g_sum[BB];
__device__ float g_sumsq[BB];
__device__ float g_rowinv[BB][CC];

// ---------------- helpers -------------------------------------------------
__device__ __forceinline__ uint32_t tf32u(float x) {
    uint32_t u;
    asm("cvt.rna.tf32.f32 %0, %1;" : "=r"(u) : "f"(x));
    return u;
}

__device__ __forceinline__ void mma_tf32(float c[4],
    uint32_t a0, uint32_t a1, uint32_t a2, uint32_t a3,
    uint32_t b0, uint32_t b1)
{
    asm volatile(
        "mma.sync.aligned.m16n8k8.row.col.f32.tf32.tf32.f32 "
        "{%0,%1,%2,%3},{%4,%5,%6,%7},{%8,%9},{%0,%1,%2,%3};"
        : "+f"(c[0]), "+f"(c[1]), "+f"(c[2]), "+f"(c[3])
        : "r"(a0), "r"(a1), "r"(a2), "r"(a3), "r"(b0), "r"(b1));
}

// swizzled k-major smem layout: row stride 136 words, column XOR by (k>>2)*8.
// Stores (k = 4*(t&3)+i) and frag loads (k = ks + lane&3, ks mult of 4) are
// both conflict-free: bank = 8*(k&3-ish) + spread column.
#define SWIDX(k, m) ((k) * 136 + ((m) ^ ((((k) >> 2) & 3) << 3)))

// ---------------- init ----------------------------------------------------
__global__ void k_init() {
    int t = threadIdx.x;
    if (t < BB) { g_sum[t] = 0.f; g_sumsq[t] = 0.f; }
}

// ---------------- kernel 1: q/k/v projections (fp32 SIMT, small) ----------
__global__ __launch_bounds__(256) void k_proj(
    const float* __restrict__ emb, const float* __restrict__ Wq,
    const float* __restrict__ Wk,  const float* __restrict__ Wv)
{
    __shared__ float embS[64][68];
    __shared__ float WS[64][68];

    int ntile = blockIdx.x, ctile = blockIdx.y, bz = blockIdx.z;
    int b = bz / 3, m = bz % 3;
    const float* W  = (m == 0) ? Wq : ((m == 1) ? Wk : Wv);
    const float* eb = emb + (size_t)((m == 0) ? (BB + b) : b) * NN * EE;
    int n0 = ntile * 64, c0 = ctile * 64;
    int t = threadIdx.x;

    #pragma unroll
    for (int r = 0; r < 4; r++) {
        int chunk = t + 256 * r;
        int row = chunk >> 4;
        int col = (chunk & 15) * 4;
        *(float4*)&embS[row][col] = *(const float4*)&eb[(size_t)(n0 + row) * EE + col];
        *(float4*)&WS[row][col]   = *(const float4*)&W[(size_t)(c0 + row) * EE + col];
    }
    __syncthreads();

    int ty = t >> 4, tx = t & 15;
    float acc[4][4] = {};
    #pragma unroll 16
    for (int e = 0; e < 64; e++) {
        float a[4], bv[4];
        #pragma unroll
        for (int i = 0; i < 4; i++) a[i]  = embS[ty + 16 * i][e];
        #pragma unroll
        for (int j = 0; j < 4; j++) bv[j] = WS[tx + 16 * j][e];
        #pragma unroll
        for (int i = 0; i < 4; i++)
            #pragma unroll
            for (int j = 0; j < 4; j++) acc[i][j] += a[i] * bv[j];
    }

    if (m == 0) {
        #pragma unroll
        for (int i = 0; i < 4; i++)
            #pragma unroll
            for (int j = 0; j < 4; j++)
                g_qT[b][c0 + tx + 16 * j][n0 + ty + 16 * i] = acc[i][j];
    } else {
        float (*bank)[DD] = (m == 1) ? g_kbank : g_vbank;
        #pragma unroll
        for (int i = 0; i < 4; i++)
            #pragma unroll
            for (int j = 0; j < 4; j++)
                bank[n0 + ty + 16 * i][b * CC + c0 + tx + 16 * j] = acc[i][j];
    }
}

// ---------------- kernel 2: scores GEMM (TF32 mma) + stats ----------------
// Per b: S(512x4096) = qT[b](512x1024) @ k_bank(1024x4096). Block 128x128xK16.
// 8 warps as 2(m) x 4(n): each warp 64m x 32n => 4x4 mma tiles of 16x8.
__global__ __launch_bounds__(256, 2) void k_scores()
{
    __shared__ float As[16 * 136];  // k-major, swizzled (transposed from qT)
    __shared__ float Bs[16 * 136];  // k-major, direct rows of k_bank
    __shared__ float red[256];

    int m0 = blockIdx.x * 128, n0 = blockIdx.y * 128, b = blockIdx.z;
    int t = threadIdx.x, lane = t & 31, warp = t >> 5;
    int wm = (warp & 1) * 64, wn = (warp >> 1) * 32;

    float acc[4][4][4] = {};

    for (int k0 = 0; k0 < NN; k0 += 16) {
        #pragma unroll
        for (int r = 0; r < 2; r++) {
            int ch = t + 256 * r;
            // A: transpose-stage 128(m) x 16(k)
            int arow = ch >> 2, akc = (ch & 3) * 4;
            float4 va = *(const float4*)&g_qT[b][m0 + arow][k0 + akc];
            As[SWIDX(akc + 0, arow)] = __uint_as_float(tf32u(va.x));
            As[SWIDX(akc + 1, arow)] = __uint_as_float(tf32u(va.y));
            As[SWIDX(akc + 2, arow)] = __uint_as_float(tf32u(va.z));
            As[SWIDX(akc + 3, arow)] = __uint_as_float(tf32u(va.w));
            // B: direct rows 16(k) x 128(n)
            int brow = ch >> 5, bcol = (ch & 31) * 4;
            float4 vb = *(const float4*)&g_kbank[k0 + brow][n0 + bcol];
            float4 cb;
            cb.x = __uint_as_float(tf32u(vb.x));
            cb.y = __uint_as_float(tf32u(vb.y));
            cb.z = __uint_as_float(tf32u(vb.z));
            cb.w = __uint_as_float(tf32u(vb.w));
            *(float4*)&Bs[brow * 136 + bcol] = cb;
        }
        __syncthreads();

        #pragma unroll
        for (int ks = 0; ks < 16; ks += 8) {
            uint32_t af[4][4], bf[4][2];
            int kk = ks + (lane & 3);
            #pragma unroll
            for (int mi = 0; mi < 4; mi++) {
                int m = wm + mi * 16 + (lane >> 2);
                af[mi][0] = __float_as_uint(As[SWIDX(kk, m)]);
                af[mi][1] = __float_as_uint(As[SWIDX(kk, m + 8)]);
                af[mi][2] = __float_as_uint(As[SWIDX(kk + 4, m)]);
                af[mi][3] = __float_as_uint(As[SWIDX(kk + 4, m + 8)]);
            }
            #pragma unroll
            for (int ni = 0; ni < 4; ni++) {
                int n = wn + ni * 8 + (lane >> 2);
                bf[ni][0] = __float_as_uint(Bs[kk * 136 + n]);
                bf[ni][1] = __float_as_uint(Bs[(kk + 4) * 136 + n]);
            }
            #pragma unroll
            for (int mi = 0; mi < 4; mi++)
                #pragma unroll
                for (int ni = 0; ni < 4; ni++)
                    mma_tf32(acc[mi][ni], af[mi][0], af[mi][1], af[mi][2], af[mi][3],
                             bf[ni][0], bf[ni][1]);
        }
        __syncthreads();
    }

    // epilogue: store scores (float2 pairs) + accumulate LN stats
    float ls = 0.f, lq = 0.f;
    #pragma unroll
    for (int mi = 0; mi < 4; mi++)
        #pragma unroll
        for (int ni = 0; ni < 4; ni++)
            #pragma unroll
            for (int h = 0; h < 2; h++) {
                int row = m0 + wm + mi * 16 + (lane >> 2) + h * 8;
                int col = n0 + wn + ni * 8 + 2 * (lane & 3);
                float v0 = acc[mi][ni][2 * h + 0];
                float v1 = acc[mi][ni][2 * h + 1];
                float2 st; st.x = v0; st.y = v1;
                *(float2*)&g_scores[b][row][col] = st;
                ls += v0 + v1;
                lq += v0 * v0 + v1 * v1;
            }

    red[t] = ls; __syncthreads();
    for (int s = 128; s > 0; s >>= 1) { if (t < s) red[t] += red[t + s]; __syncthreads(); }
    if (t == 0) atomicAdd(&g_sum[b], red[0]);
    __syncthreads();
    red[t] = lq; __syncthreads();
    for (int s = 128; s > 0; s >>= 1) { if (t < s) red[t] += red[t + s]; __syncthreads(); }
    if (t == 0) atomicAdd(&g_sumsq[b], red[0]);
}

// ---------------- kernel 3: LN + exp + row-sum ----------------------------
__global__ __launch_bounds__(256) void k_softmax()
{
    int c = blockIdx.x, b = blockIdx.y;
    int t = threadIdx.x;
    __shared__ float red[256];

    const float invCD = 1.0f / ((float)CC * (float)DD);
    float mean = g_sum[b] * invCD;
    float var  = g_sumsq[b] * invCD - mean * mean;
    float rstd = rsqrtf(var + EPS_LN);

    float* row = &g_scores[b][c][0];
    float ls = 0.f;
    #pragma unroll
    for (int r = 0; r < 4; r++) {
        int idx = (t + 256 * r) * 4;
        float4 v = *(float4*)&row[idx];
        v.x = __expf((v.x - mean) * rstd);
        v.y = __expf((v.y - mean) * rstd);
        v.z = __expf((v.z - mean) * rstd);
        v.w = __expf((v.w - mean) * rstd);
        *(float4*)&row[idx] = v;
        ls += v.x + v.y + v.z + v.w;
    }
    red[t] = ls; __syncthreads();
    for (int s = 128; s > 0; s >>= 1) { if (t < s) red[t] += red[t + s]; __syncthreads(); }
    if (t == 0) g_rowinv[b][c] = 1.0f / red[0];
}

// ---------------- kernel 4: ctx GEMM (TF32 mma) ---------------------------
// Per b: ctx(512x1024) = expS(512x4096) @ v_bank^T(4096x1024).
// A = g_scores rows (k contiguous) -> transpose-stage. B = v_bank[n][k] rows
// (k contiguous) -> transpose-stage. Both swizzled k-major.
__global__ __launch_bounds__(256, 2) void k_ctx()
{
    __shared__ float As[16 * 136];
    __shared__ float Bs[16 * 136];

    int m0 = blockIdx.x * 128, n0 = blockIdx.y * 128, b = blockIdx.z;
    int t = threadIdx.x, lane = t & 31, warp = t >> 5;
    int wm = (warp & 1) * 64, wn = (warp >> 1) * 32;

    float acc[4][4][4] = {};

    for (int k0 = 0; k0 < DD; k0 += 16) {
        #pragma unroll
        for (int r = 0; r < 2; r++) {
            int ch = t + 256 * r;
            int arow = ch >> 2, akc = (ch & 3) * 4;
            float4 va = *(const float4*)&g_scores[b][m0 + arow][k0 + akc];
            As[SWIDX(akc + 0, arow)] = __uint_as_float(tf32u(va.x));
            As[SWIDX(akc + 1, arow)] = __uint_as_float(tf32u(va.y));
            As[SWIDX(akc + 2, arow)] = __uint_as_float(tf32u(va.z));
            As[SWIDX(akc + 3, arow)] = __uint_as_float(tf32u(va.w));
            float4 vb = *(const float4*)&g_vbank[n0 + arow][k0 + akc];
            Bs[SWIDX(akc + 0, arow)] = __uint_as_float(tf32u(vb.x));
            Bs[SWIDX(akc + 1, arow)] = __uint_as_float(tf32u(vb.y));
            Bs[SWIDX(akc + 2, arow)] = __uint_as_float(tf32u(vb.z));
            Bs[SWIDX(akc + 3, arow)] = __uint_as_float(tf32u(vb.w));
        }
        __syncthreads();

        #pragma unroll
        for (int ks = 0; ks < 16; ks += 8) {
            uint32_t af[4][4], bf[4][2];
            int kk = ks + (lane & 3);
            #pragma unroll
            for (int mi = 0; mi < 4; mi++) {
                int m = wm + mi * 16 + (lane >> 2);
                af[mi][0] = __float_as_uint(As[SWIDX(kk, m)]);
                af[mi][1] = __float_as_uint(As[SWIDX(kk, m + 8)]);
                af[mi][2] = __float_as_uint(As[SWIDX(kk + 4, m)]);
                af[mi][3] = __float_as_uint(As[SWIDX(kk + 4, m + 8)]);
            }
            #pragma unroll
            for (int ni = 0; ni < 4; ni++) {
                int n = wn + ni * 8 + (lane >> 2);
                bf[ni][0] = __float_as_uint(Bs[SWIDX(kk, n)]);
                bf[ni][1] = __float_as_uint(Bs[SWIDX(kk + 4, n)]);
            }
            #pragma unroll
            for (int mi = 0; mi < 4; mi++)
                #pragma unroll
                for (int ni = 0; ni < 4; ni++)
                    mma_tf32(acc[mi][ni], af[mi][0], af[mi][1], af[mi][2], af[mi][3],
                             bf[ni][0], bf[ni][1]);
        }
        __syncthreads();
    }

    #pragma unroll
    for (int mi = 0; mi < 4; mi++)
        #pragma unroll
        for (int ni = 0; ni < 4; ni++)
            #pragma unroll
            for (int h = 0; h < 2; h++) {
                int row = m0 + wm + mi * 16 + (lane >> 2) + h * 8;
                int col = n0 + wn + ni * 8 + 2 * (lane & 3);
                float inv = g_rowinv[b][row];
                float2 st;
                st.x = acc[mi][ni][2 * h + 0] * inv;
                st.y = acc[mi][ni][2 * h + 1] * inv;
                *(float2*)&g_ctx[b][row][col] = st;
            }
}

// ---------------- kernel 5: output projection (fp32, small) ---------------
__global__ __launch_bounds__(256) void k_out(
    const float* __restrict__ Wo, float* __restrict__ out)
{
    __shared__ float ctxS[16][68];
    __shared__ float WoS[16][68];

    int n0 = blockIdx.x * 64;
    int b  = blockIdx.y;
    int t = threadIdx.x, ty = t >> 4, tx = t & 15;

    float acc[4][4] = {};
    for (int c0 = 0; c0 < CC; c0 += 16) {
        {
            int row = t >> 4, col = (t & 15) * 4;
            *(float4*)&ctxS[row][col] = *(const float4*)&g_ctx[b][c0 + row][n0 + col];
            int e = t >> 2, cc4 = (t & 3) * 4;
            float4 w = *(const float4*)&Wo[(size_t)e * CC + c0 + cc4];
            WoS[cc4 + 0][e] = w.x; WoS[cc4 + 1][e] = w.y;
            WoS[cc4 + 2][e] = w.z; WoS[cc4 + 3][e] = w.w;
        }
        __syncthreads();
        #pragma unroll
        for (int cc = 0; cc < 16; cc++) {
            float a[4], bv[4];
            #pragma unroll
            for (int i = 0; i < 4; i++) a[i]  = ctxS[cc][ty + 16 * i];
            #pragma unroll
            for (int j = 0; j < 4; j++) bv[j] = WoS[cc][tx + 16 * j];
            #pragma unroll
            for (int i = 0; i < 4; i++)
                #pragma unroll
                for (int j = 0; j < 4; j++) acc[i][j] += a[i] * bv[j];
        }
        __syncthreads();
    }
    #pragma unroll
    for (int i = 0; i < 4; i++)
        #pragma unroll
        for (int j = 0; j < 4; j++)
            out[((size_t)b * NN + n0 + ty + 16 * i) * EE + tx + 16 * j] = acc[i][j];
}

// ---------------- launch ---------------------------------------------------
extern "C" void kernel_launch(void* const* d_in, const int* in_sizes, int n_in,
                              void* d_out, int out_size)
{
    const float* emb = (const float*)d_in[0];
    const float* Wq  = (const float*)d_in[1];
    const float* Wk  = (const float*)d_in[2];
    const float* Wv  = (const float*)d_in[3];
    const float* Wo  = (const float*)d_in[4];
    float* out = (float*)d_out;

    k_init<<<1, 32>>>();

    dim3 g1(16, 8, 24);
    k_proj<<<g1, 256>>>(emb, Wq, Wk, Wv);

    dim3 g2(4, 32, 8);           // 512/128 x 4096/128 x B
    k_scores<<<g2, 256>>>();

    dim3 g3(512, 8);
    k_softmax<<<g3, 256>>>();

    dim3 g4(4, 8, 8);            // 512/128 x 1024/128 x B
    k_ctx<<<g4, 256>>>();

    dim3 g5(16, 8);
    k_out<<<g5, 256>>>(Wo, out);
}